// round 7
// baseline (speedup 1.0000x reference)
#include <cuda_runtime.h>
#include <math.h>

#define BB   128      // batch
#define TT   1998     // timesteps
#define HH   256      // hidden
#define UU   256      // units
#define KTOP 1332     // top-k kept

// ---------------- scratch (device globals; no allocation allowed) ----------
__device__ float g_W1T[HH * UU];      // W1 transposed: [h][u]
__device__ float g_qproj[BB * UU];    // query @ W2^T + b2
__device__ float g_convo[BB * TT];    // conv output (only tap 3 is live)
__device__ float g_energy[BB * TT];   // pre-mask score
__device__ float g_denom[TT];         // sum_b sigmoid(masked score)

// ---------------- W1 transpose ------------------------------------------
__global__ void k_transpose_w1(const float* __restrict__ W1) {
    __shared__ float tile[32][33];
    int u0 = blockIdx.x * 32, h0 = blockIdx.y * 32;
    int tx = threadIdx.x, ty = threadIdx.y;     // block (32, 8)
    for (int i = ty; i < 32; i += 8)
        tile[i][tx] = W1[(u0 + i) * HH + h0 + tx];
    __syncthreads();
    for (int i = ty; i < 32; i += 8)
        g_W1T[(size_t)(h0 + i) * UU + u0 + tx] = tile[tx][i];
}

// ---------------- q projection -------------------------------------------
__global__ void k_qproj(const float* __restrict__ query,
                        const float* __restrict__ W2w,
                        const float* __restrict__ W2b) {
    int b = blockIdx.x;
    int u = threadIdx.x;                         // blockDim = 256 == HH
    __shared__ float q[HH];
    q[u] = query[b * HH + u];
    __syncthreads();
    float acc = W2b[u];
    const float4* w = (const float4*)(W2w + (size_t)u * HH);
#pragma unroll 8
    for (int h4 = 0; h4 < HH / 4; ++h4) {
        float4 wv = w[h4];
        acc += wv.x * q[h4 * 4 + 0] + wv.y * q[h4 * 4 + 1]
             + wv.z * q[h4 * 4 + 2] + wv.w * q[h4 * 4 + 3];
    }
    g_qproj[b * UU + u] = acc;
}

// ---------------- conv (tap-3 slice GEMM) --------------------------------
#define CONV_BO 8
#define CONV_CH 64
__global__ void k_convo(const float* __restrict__ prev,
                        const float* __restrict__ convw) {
    int o0 = blockIdx.x * CONV_BO;
    __shared__ float ps[BB][CONV_CH + 1];
    __shared__ float ws[CONV_BO][CONV_CH + 1];
    int tid = threadIdx.x;                      // 256
    int bb  = tid & 127;
    int og  = tid >> 7;                         // 0 or 1 -> 4 o's each
    float acc[4] = {0.f, 0.f, 0.f, 0.f};
    for (int i0 = 0; i0 < TT; i0 += CONV_CH) {
        int len = min(CONV_CH, TT - i0);
        __syncthreads();
        for (int idx = tid; idx < BB * CONV_CH; idx += 256) {
            int r = idx / CONV_CH, c = idx % CONV_CH;
            ps[r][c] = (c < len) ? prev[(size_t)r * TT + i0 + c] : 0.f;
        }
        for (int idx = tid; idx < CONV_BO * CONV_CH; idx += 256) {
            int r = idx / CONV_CH, c = idx % CONV_CH;
            int o = o0 + r;
            ws[r][c] = (c < len && o < TT)
                       ? convw[((size_t)o * TT + i0 + c) * 7 + 3] : 0.f;
        }
        __syncthreads();
#pragma unroll 4
        for (int c = 0; c < CONV_CH; ++c) {
            float p = ps[bb][c];
#pragma unroll
            for (int j = 0; j < 4; ++j) acc[j] += p * ws[og * 4 + j][c];
        }
    }
    for (int j = 0; j < 4; ++j) {
        int o = o0 + og * 4 + j;
        if (o < TT) g_convo[(size_t)bb * TT + o] = acc[j];
    }
}

// ---------------- energy init (score bias V_b) ----------------------------
__global__ void k_init_energy(const float* __restrict__ Vb) {
    int i = blockIdx.x * 256 + threadIdx.x;
    if (i < BB * TT) g_energy[i] = Vb[0];
}

// ---------------- fused energy GEMM: tanh(values@W1T + ...) @ Vw ----------
// block tile 128(M=t) x 128(N=u), K=256 in steps of 8, double-buffered.
__global__ __launch_bounds__(256, 2)
void k_energy(const float* __restrict__ values,
              const float* __restrict__ W1b,
              const float* __restrict__ Vw,
              const float* __restrict__ locproj) {
    __shared__ float As[2][8][132];
    __shared__ float Bs[2][8][132];
    __shared__ float s_qp[128], s_lp[128], s_vw[128], s_w1b[128];
    __shared__ float s_red[128][17];

    int b   = blockIdx.y;
    int t0  = blockIdx.x * 128;
    int n0  = blockIdx.z * 128;
    int tid = threadIdx.x;

    if (tid < 128) {
        int u = n0 + tid;
        s_qp[tid]  = g_qproj[b * UU + u];
        s_lp[tid]  = locproj[u];
        s_vw[tid]  = Vw[u];
        s_w1b[tid] = W1b[u];
    }

    const float* Abase = values + (size_t)b * TT * HH;
    int arow = tid >> 1;               // 0..127 (m)
    int ac4  = (tid & 1) * 4;          // 0 or 4 (k within 8)
    int t_a  = t0 + arow;
    bool avalid = (t_a < TT);
    const float* Aptr = Abase + (size_t)t_a * HH + ac4;

    int brow = tid >> 5;               // 0..7 (k)
    int bc   = (tid & 31) * 4;         // 0..124 (n)
    const float* Bptr = g_W1T + (size_t)brow * UU + n0 + bc;

    float acc[8][8];
#pragma unroll
    for (int i = 0; i < 8; ++i)
#pragma unroll
        for (int j = 0; j < 8; ++j) acc[i][j] = 0.f;

    {   // first tile
        float4 av = avalid ? *(const float4*)Aptr : make_float4(0, 0, 0, 0);
        As[0][ac4 + 0][arow] = av.x; As[0][ac4 + 1][arow] = av.y;
        As[0][ac4 + 2][arow] = av.z; As[0][ac4 + 3][arow] = av.w;
        *(float4*)&Bs[0][brow][bc] = *(const float4*)Bptr;
    }
    __syncthreads();

    int tx = tid & 15, ty = tid >> 4;
#pragma unroll 1
    for (int kt = 0; kt < 32; ++kt) {
        int buf = kt & 1;
        float4 av = make_float4(0, 0, 0, 0), bv = make_float4(0, 0, 0, 0);
        if (kt < 31) {
            if (avalid) av = *(const float4*)(Aptr + (kt + 1) * 8);
            bv = *(const float4*)(Bptr + (size_t)(kt + 1) * 8 * UU);
        }
#pragma unroll
        for (int k = 0; k < 8; ++k) {
            float4 a0 = *(const float4*)&As[buf][k][ty * 8];
            float4 a1 = *(const float4*)&As[buf][k][ty * 8 + 4];
            float4 b0 = *(const float4*)&Bs[buf][k][tx * 8];
            float4 b1 = *(const float4*)&Bs[buf][k][tx * 8 + 4];
            float ar[8] = {a0.x, a0.y, a0.z, a0.w, a1.x, a1.y, a1.z, a1.w};
            float br[8] = {b0.x, b0.y, b0.z, b0.w, b1.x, b1.y, b1.z, b1.w};
#pragma unroll
            for (int i = 0; i < 8; ++i)
#pragma unroll
                for (int j = 0; j < 8; ++j) acc[i][j] += ar[i] * br[j];
        }
        if (kt < 31) {
            int nb = buf ^ 1;
            As[nb][ac4 + 0][arow] = av.x; As[nb][ac4 + 1][arow] = av.y;
            As[nb][ac4 + 2][arow] = av.z; As[nb][ac4 + 3][arow] = av.w;
            *(float4*)&Bs[nb][brow][bc] = bv;
        }
        __syncthreads();
    }

    // epilogue: +bias +qproj +convo*locproj, tanh, dot with Vw, row-reduce
    float cv[8];
#pragma unroll
    for (int i = 0; i < 8; ++i) {
        int t = t0 + ty * 8 + i;
        cv[i] = (t < TT) ? g_convo[(size_t)b * TT + t] : 0.f;
    }
#pragma unroll
    for (int i = 0; i < 8; ++i) {
        float s = 0.f;
#pragma unroll
        for (int j = 0; j < 8; ++j) {
            int nl = tx * 8 + j;
            float e = acc[i][j] + s_w1b[nl] + s_qp[nl] + cv[i] * s_lp[nl];
            s += s_vw[nl] * tanhf(e);
        }
        s_red[ty * 8 + i][tx] = s;
    }
    __syncthreads();
    if (tid < 128) {
        float s = 0.f;
#pragma unroll
        for (int x = 0; x < 16; ++x) s += s_red[tid][x];
        int t = t0 + tid;
        if (t < TT) atomicAdd(&g_energy[(size_t)b * TT + t], s);
    }
}

// ---------------- per-batch top-K mask (radix select, exact ties) ---------
__device__ __forceinline__ unsigned f2o(float f) {
    unsigned u = __float_as_uint(f);
    return (u & 0x80000000u) ? ~u : (u | 0x80000000u);
}

__global__ void k_topk(float* __restrict__ score_out) {
    int b = blockIdx.x;
    __shared__ unsigned keys[TT];
    __shared__ unsigned hist[256];
    __shared__ unsigned s_prefix, s_rem, cGreater, eqKeep;
    __shared__ unsigned eqflag[256];
    int tid = threadIdx.x;

    for (int i = tid; i < TT; i += 256) keys[i] = f2o(g_energy[(size_t)b * TT + i]);
    if (tid == 0) { s_prefix = 0u; s_rem = KTOP; cGreater = 0u; eqKeep = 0u; }
    __syncthreads();

    for (int pass = 0; pass < 4; ++pass) {
        int shift = 24 - pass * 8;
        if (tid < 256) hist[tid] = 0u;
        __syncthreads();
        unsigned pfx  = s_prefix;
        unsigned mask = (pass == 0) ? 0u : (0xFFFFFFFFu << (shift + 8));
        for (int i = tid; i < TT; i += 256) {
            unsigned k = keys[i];
            if ((k & mask) == pfx) atomicAdd(&hist[(k >> shift) & 255u], 1u);
        }
        __syncthreads();
        if (tid == 0) {
            unsigned rem0 = s_rem, acc = 0u;
            int d = 255;
            for (; d > 0; --d) {
                if (acc + hist[d] >= rem0) break;
                acc += hist[d];
            }
            s_rem    = rem0 - acc;
            s_prefix = s_prefix | ((unsigned)d << shift);
        }
        __syncthreads();
    }
    unsigned thr = s_prefix;     // exact K-th largest key

    for (int i = tid; i < TT; i += 256)
        if (keys[i] > thr) atomicAdd(&cGreater, 1u);
    __syncthreads();
    unsigned need = KTOP - cGreater;   // #(== thr) to keep, lowest index first

    for (int base = 0; base < TT; base += 256) {
        int i = base + tid;
        bool eq = (i < TT) && (keys[i] == thr);
        eqflag[tid] = eq ? 1u : 0u;
        __syncthreads();
        for (int off = 1; off < 256; off <<= 1) {   // inclusive scan
            unsigned v = (tid >= off) ? eqflag[tid - off] : 0u;
            __syncthreads();
            eqflag[tid] += v;
            __syncthreads();
        }
        unsigned before = eqKeep + eqflag[tid] - (eq ? 1u : 0u);
        if (i < TT) {
            bool keep = (keys[i] > thr) || (eq && before < need);
            score_out[(size_t)b * TT + i] = keep ? g_energy[(size_t)b * TT + i] : 0.f;
        }
        __syncthreads();
        if (tid == 255) eqKeep += eqflag[255];
        __syncthreads();
    }
}

// ---------------- denom over batch axis ----------------------------------
__global__ void k_denom(const float* __restrict__ score) {
    int t = blockIdx.x * 256 + threadIdx.x;
    if (t >= TT) return;
    float s = 0.f;
    for (int b = 0; b < BB; ++b) {
        float x = score[(size_t)b * TT + t];
        s += 1.f / (1.f + expf(-x));
    }
    g_denom[t] = s;
}

// ---------------- attention weights + context ----------------------------
__global__ void k_final(const float* __restrict__ values,
                        const float* __restrict__ score,
                        float* __restrict__ attn_out,
                        float* __restrict__ ctx_out) {
    int b = blockIdx.x;
    int h = threadIdx.x;                 // 256
    __shared__ float wch[256];
    float acc = 0.f;
    for (int t0 = 0; t0 < TT; t0 += 256) {
        int tt = t0 + h;
        __syncthreads();
        if (tt < TT) {
            float x = score[(size_t)b * TT + tt];
            float w = (1.f / (1.f + expf(-x))) / g_denom[tt];
            wch[h] = w;
            attn_out[(size_t)b * TT + tt] = w;
        }
        __syncthreads();
        int len = min(256, TT - t0);
        const float* vp = values + (size_t)b * TT * HH + (size_t)t0 * HH + h;
#pragma unroll 4
        for (int j = 0; j < len; ++j)
            acc += wch[j] * vp[(size_t)j * HH];
    }
    ctx_out[b * HH + h] = acc;
}

// ---------------- launch -------------------------------------------------
extern "C" void kernel_launch(void* const* d_in, const int* in_sizes, int n_in,
                              void* d_out, int out_size) {
    const float* query   = (const float*)d_in[0];
    const float* values  = (const float*)d_in[1];
    const float* prev    = (const float*)d_in[2];
    const float* W1w     = (const float*)d_in[3];
    const float* W1b     = (const float*)d_in[4];
    const float* W2w     = (const float*)d_in[5];
    const float* W2b     = (const float*)d_in[6];
    const float* Vw      = (const float*)d_in[7];
    const float* Vb      = (const float*)d_in[8];
    const float* convw   = (const float*)d_in[9];
    const float* locproj = (const float*)d_in[10];

    float* out   = (float*)d_out;
    float* ctx   = out;                       // [B, H]
    float* attn  = out + BB * HH;             // [B, T, 1]
    float* score = out + BB * HH + BB * TT;   // [B, T, 1]

    k_transpose_w1<<<dim3(UU / 32, HH / 32), dim3(32, 8)>>>(W1w);
    k_qproj<<<BB, 256>>>(query, W2w, W2b);
    k_convo<<<(TT + CONV_BO - 1) / CONV_BO, 256>>>(prev, convw);
    k_init_energy<<<(BB * TT + 255) / 256, 256>>>(Vb);
    k_energy<<<dim3(16, BB, 2), 256>>>(values, W1b, Vw, locproj);
    k_topk<<<BB, 256>>>(score);
    k_denom<<<(TT + 255) / 256, 256>>>(score);
    k_final<<<BB, 256>>>(values, score, attn, ctx);
}

// round 8
// speedup vs baseline: 1.0006x; 1.0006x over previous
#include <cuda_runtime.h>
#include <math.h>

#define BB   128      // batch
#define TT   1998     // timesteps
#define HH   256      // hidden
#define UU   256      // units
#define KTOP 1332     // top-k kept

// ---------------- scratch (device globals; no allocation allowed) ----------
__device__ float g_W1T[HH * UU];      // W1 transposed: [h][u]
__device__ float g_qproj[BB * UU];    // query @ W2^T + b2
__device__ float g_convo[BB * TT];    // conv output (only tap 3 is live)
__device__ float g_energy[BB * TT];   // pre-mask score
__device__ float g_denom[TT];         // sum_b sigmoid(masked score)

// ---------------- W1 transpose ------------------------------------------
__global__ void k_transpose_w1(const float* __restrict__ W1) {
    __shared__ float tile[32][33];
    int u0 = blockIdx.x * 32, h0 = blockIdx.y * 32;
    int tx = threadIdx.x, ty = threadIdx.y;     // block (32, 8)
    for (int i = ty; i < 32; i += 8)
        tile[i][tx] = W1[(u0 + i) * HH + h0 + tx];
    __syncthreads();
    for (int i = ty; i < 32; i += 8)
        g_W1T[(size_t)(h0 + i) * UU + u0 + tx] = tile[tx][i];
}

// ---------------- q projection -------------------------------------------
__global__ void k_qproj(const float* __restrict__ query,
                        const float* __restrict__ W2w,
                        const float* __restrict__ W2b) {
    int b = blockIdx.x;
    int u = threadIdx.x;                         // blockDim = 256 == HH
    __shared__ float q[HH];
    q[u] = query[b * HH + u];
    __syncthreads();
    float acc = W2b[u];
    const float4* w = (const float4*)(W2w + (size_t)u * HH);
#pragma unroll 8
    for (int h4 = 0; h4 < HH / 4; ++h4) {
        float4 wv = w[h4];
        acc += wv.x * q[h4 * 4 + 0] + wv.y * q[h4 * 4 + 1]
             + wv.z * q[h4 * 4 + 2] + wv.w * q[h4 * 4 + 3];
    }
    g_qproj[b * UU + u] = acc;
}

// ---------------- conv (tap-3 slice GEMM) --------------------------------
#define CONV_BO 8
#define CONV_CH 64
__global__ void k_convo(const float* __restrict__ prev,
                        const float* __restrict__ convw) {
    int o0 = blockIdx.x * CONV_BO;
    __shared__ float ps[BB][CONV_CH + 1];
    __shared__ float ws[CONV_BO][CONV_CH + 1];
    int tid = threadIdx.x;                      // 256
    int bb  = tid & 127;
    int og  = tid >> 7;                         // 0 or 1 -> 4 o's each
    float acc[4] = {0.f, 0.f, 0.f, 0.f};
    for (int i0 = 0; i0 < TT; i0 += CONV_CH) {
        int len = min(CONV_CH, TT - i0);
        __syncthreads();
        for (int idx = tid; idx < BB * CONV_CH; idx += 256) {
            int r = idx / CONV_CH, c = idx % CONV_CH;
            ps[r][c] = (c < len) ? prev[(size_t)r * TT + i0 + c] : 0.f;
        }
        for (int idx = tid; idx < CONV_BO * CONV_CH; idx += 256) {
            int r = idx / CONV_CH, c = idx % CONV_CH;
            int o = o0 + r;
            ws[r][c] = (c < len && o < TT)
                       ? convw[((size_t)o * TT + i0 + c) * 7 + 3] : 0.f;
        }
        __syncthreads();
#pragma unroll 4
        for (int c = 0; c < CONV_CH; ++c) {
            float p = ps[bb][c];
#pragma unroll
            for (int j = 0; j < 4; ++j) acc[j] += p * ws[og * 4 + j][c];
        }
    }
    for (int j = 0; j < 4; ++j) {
        int o = o0 + og * 4 + j;
        if (o < TT) g_convo[(size_t)bb * TT + o] = acc[j];
    }
}

// ---------------- energy init (score bias V_b) ----------------------------
__global__ void k_init_energy(const float* __restrict__ Vb) {
    int i = blockIdx.x * 256 + threadIdx.x;
    if (i < BB * TT) g_energy[i] = Vb[0];
}

// ---------------- fused energy GEMM: tanh(values@W1T + ...) @ Vw ----------
// block tile 128(M=t) x 128(N=u), K=256 in steps of 8, double-buffered.
__global__ __launch_bounds__(256, 2)
void k_energy(const float* __restrict__ values,
              const float* __restrict__ W1b,
              const float* __restrict__ Vw,
              const float* __restrict__ locproj) {
    __shared__ float As[2][8][132];
    __shared__ float Bs[2][8][132];
    __shared__ float s_qp[128], s_lp[128], s_vw[128], s_w1b[128];
    __shared__ float s_red[128][17];

    int b   = blockIdx.y;
    int t0  = blockIdx.x * 128;
    int n0  = blockIdx.z * 128;
    int tid = threadIdx.x;

    if (tid < 128) {
        int u = n0 + tid;
        s_qp[tid]  = g_qproj[b * UU + u];
        s_lp[tid]  = locproj[u];
        s_vw[tid]  = Vw[u];
        s_w1b[tid] = W1b[u];
    }

    const float* Abase = values + (size_t)b * TT * HH;
    int arow = tid >> 1;               // 0..127 (m)
    int ac4  = (tid & 1) * 4;          // 0 or 4 (k within 8)
    int t_a  = t0 + arow;
    bool avalid = (t_a < TT);
    const float* Aptr = Abase + (size_t)t_a * HH + ac4;

    int brow = tid >> 5;               // 0..7 (k)
    int bc   = (tid & 31) * 4;         // 0..124 (n)
    const float* Bptr = g_W1T + (size_t)brow * UU + n0 + bc;

    float acc[8][8];
#pragma unroll
    for (int i = 0; i < 8; ++i)
#pragma unroll
        for (int j = 0; j < 8; ++j) acc[i][j] = 0.f;

    {   // first tile
        float4 av = avalid ? *(const float4*)Aptr : make_float4(0, 0, 0, 0);
        As[0][ac4 + 0][arow] = av.x; As[0][ac4 + 1][arow] = av.y;
        As[0][ac4 + 2][arow] = av.z; As[0][ac4 + 3][arow] = av.w;
        *(float4*)&Bs[0][brow][bc] = *(const float4*)Bptr;
    }
    __syncthreads();

    int tx = tid & 15, ty = tid >> 4;
#pragma unroll 1
    for (int kt = 0; kt < 32; ++kt) {
        int buf = kt & 1;
        float4 av = make_float4(0, 0, 0, 0), bv = make_float4(0, 0, 0, 0);
        if (kt < 31) {
            if (avalid) av = *(const float4*)(Aptr + (kt + 1) * 8);
            bv = *(const float4*)(Bptr + (size_t)(kt + 1) * 8 * UU);
        }
#pragma unroll
        for (int k = 0; k < 8; ++k) {
            float4 a0 = *(const float4*)&As[buf][k][ty * 8];
            float4 a1 = *(const float4*)&As[buf][k][ty * 8 + 4];
            float4 b0 = *(const float4*)&Bs[buf][k][tx * 8];
            float4 b1 = *(const float4*)&Bs[buf][k][tx * 8 + 4];
            float ar[8] = {a0.x, a0.y, a0.z, a0.w, a1.x, a1.y, a1.z, a1.w};
            float br[8] = {b0.x, b0.y, b0.z, b0.w, b1.x, b1.y, b1.z, b1.w};
#pragma unroll
            for (int i = 0; i < 8; ++i)
#pragma unroll
                for (int j = 0; j < 8; ++j) acc[i][j] += ar[i] * br[j];
        }
        if (kt < 31) {
            int nb = buf ^ 1;
            As[nb][ac4 + 0][arow] = av.x; As[nb][ac4 + 1][arow] = av.y;
            As[nb][ac4 + 2][arow] = av.z; As[nb][ac4 + 3][arow] = av.w;
            *(float4*)&Bs[nb][brow][bc] = bv;
        }
        __syncthreads();
    }

    // epilogue: +bias +qproj +convo*locproj, tanh, dot with Vw, row-reduce
    float cv[8];
#pragma unroll
    for (int i = 0; i < 8; ++i) {
        int t = t0 + ty * 8 + i;
        cv[i] = (t < TT) ? g_convo[(size_t)b * TT + t] : 0.f;
    }
#pragma unroll
    for (int i = 0; i < 8; ++i) {
        float s = 0.f;
#pragma unroll
        for (int j = 0; j < 8; ++j) {
            int nl = tx * 8 + j;
            float e = acc[i][j] + s_w1b[nl] + s_qp[nl] + cv[i] * s_lp[nl];
            s += s_vw[nl] * tanhf(e);
        }
        s_red[ty * 8 + i][tx] = s;
    }
    __syncthreads();
    if (tid < 128) {
        float s = 0.f;
#pragma unroll
        for (int x = 0; x < 16; ++x) s += s_red[tid][x];
        int t = t0 + tid;
        if (t < TT) atomicAdd(&g_energy[(size_t)b * TT + t], s);
    }
}

// ---------------- per-batch top-K mask (radix select, exact ties) ---------
__device__ __forceinline__ unsigned f2o(float f) {
    unsigned u = __float_as_uint(f);
    return (u & 0x80000000u) ? ~u : (u | 0x80000000u);
}

__global__ void k_topk(float* __restrict__ score_out) {
    int b = blockIdx.x;
    __shared__ unsigned keys[TT];
    __shared__ unsigned hist[256];
    __shared__ unsigned s_prefix, s_rem, cGreater, eqKeep;
    __shared__ unsigned eqflag[256];
    int tid = threadIdx.x;

    for (int i = tid; i < TT; i += 256) keys[i] = f2o(g_energy[(size_t)b * TT + i]);
    if (tid == 0) { s_prefix = 0u; s_rem = KTOP; cGreater = 0u; eqKeep = 0u; }
    __syncthreads();

    for (int pass = 0; pass < 4; ++pass) {
        int shift = 24 - pass * 8;
        if (tid < 256) hist[tid] = 0u;
        __syncthreads();
        unsigned pfx  = s_prefix;
        unsigned mask = (pass == 0) ? 0u : (0xFFFFFFFFu << (shift + 8));
        for (int i = tid; i < TT; i += 256) {
            unsigned k = keys[i];
            if ((k & mask) == pfx) atomicAdd(&hist[(k >> shift) & 255u], 1u);
        }
        __syncthreads();
        if (tid == 0) {
            unsigned rem0 = s_rem, acc = 0u;
            int d = 255;
            for (; d > 0; --d) {
                if (acc + hist[d] >= rem0) break;
                acc += hist[d];
            }
            s_rem    = rem0 - acc;
            s_prefix = s_prefix | ((unsigned)d << shift);
        }
        __syncthreads();
    }
    unsigned thr = s_prefix;     // exact K-th largest key

    for (int i = tid; i < TT; i += 256)
        if (keys[i] > thr) atomicAdd(&cGreater, 1u);
    __syncthreads();
    unsigned need = KTOP - cGreater;   // #(== thr) to keep, lowest index first

    for (int base = 0; base < TT; base += 256) {
        int i = base + tid;
        bool eq = (i < TT) && (keys[i] == thr);
        eqflag[tid] = eq ? 1u : 0u;
        __syncthreads();
        for (int off = 1; off < 256; off <<= 1) {   // inclusive scan
            unsigned v = (tid >= off) ? eqflag[tid - off] : 0u;
            __syncthreads();
            eqflag[tid] += v;
            __syncthreads();
        }
        unsigned before = eqKeep + eqflag[tid] - (eq ? 1u : 0u);
        if (i < TT) {
            bool keep = (keys[i] > thr) || (eq && before < need);
            score_out[(size_t)b * TT + i] = keep ? g_energy[(size_t)b * TT + i] : 0.f;
        }
        __syncthreads();
        if (tid == 255) eqKeep += eqflag[255];
        __syncthreads();
    }
}

// ---------------- denom over batch axis ----------------------------------
__global__ void k_denom(const float* __restrict__ score) {
    int t = blockIdx.x * 256 + threadIdx.x;
    if (t >= TT) return;
    float s = 0.f;
    for (int b = 0; b < BB; ++b) {
        float x = score[(size_t)b * TT + t];
        s += 1.f / (1.f + expf(-x));
    }
    g_denom[t] = s;
}

// ---------------- attention weights + context ----------------------------
__global__ void k_final(const float* __restrict__ values,
                        const float* __restrict__ score,
                        float* __restrict__ attn_out,
                        float* __restrict__ ctx_out) {
    int b = blockIdx.x;
    int h = threadIdx.x;                 // 256
    __shared__ float wch[256];
    float acc = 0.f;
    for (int t0 = 0; t0 < TT; t0 += 256) {
        int tt = t0 + h;
        __syncthreads();
        if (tt < TT) {
            float x = score[(size_t)b * TT + tt];
            float w = (1.f / (1.f + expf(-x))) / g_denom[tt];
            wch[h] = w;
            attn_out[(size_t)b * TT + tt] = w;
        }
        __syncthreads();
        int len = min(256, TT - t0);
        const float* vp = values + (size_t)b * TT * HH + (size_t)t0 * HH + h;
#pragma unroll 4
        for (int j = 0; j < len; ++j)
            acc += wch[j] * vp[(size_t)j * HH];
    }
    ctx_out[b * HH + h] = acc;
}

// ---------------- launch -------------------------------------------------
extern "C" void kernel_launch(void* const* d_in, const int* in_sizes, int n_in,
                              void* d_out, int out_size) {
    const float* query   = (const float*)d_in[0];
    const float* values  = (const float*)d_in[1];
    const float* prev    = (const float*)d_in[2];
    const float* W1w     = (const float*)d_in[3];
    const float* W1b     = (const float*)d_in[4];
    const float* W2w     = (const float*)d_in[5];
    const float* W2b     = (const float*)d_in[6];
    const float* Vw      = (const float*)d_in[7];
    const float* Vb      = (const float*)d_in[8];
    const float* convw   = (const float*)d_in[9];
    const float* locproj = (const float*)d_in[10];

    float* out   = (float*)d_out;
    float* ctx   = out;                       // [B, H]
    float* attn  = out + BB * HH;             // [B, T, 1]
    float* score = out + BB * HH + BB * TT;   // [B, T, 1]

    k_transpose_w1<<<dim3(UU / 32, HH / 32), dim3(32, 8)>>>(W1w);
    k_qproj<<<BB, 256>>>(query, W2w, W2b);
    k_convo<<<(TT + CONV_BO - 1) / CONV_BO, 256>>>(prev, convw);
    k_init_energy<<<(BB * TT + 255) / 256, 256>>>(Vb);
    k_energy<<<dim3(16, BB, 2), 256>>>(values, W1b, Vw, locproj);
    k_topk<<<BB, 256>>>(score);
    k_denom<<<(TT + 255) / 256, 256>>>(score);
    k_final<<<BB, 256>>>(values, score, attn, ctx);
}